// round 12
// baseline (speedup 1.0000x reference)
#include <cuda_runtime.h>
#include <cuda_bf16.h>
#include <cuda_fp16.h>
#include <math.h>

// Problem constants
#define PH     5
#define NCOIL  16          // ch*d = 8*2
#define NIM    320         // H = W
#define KOS    640         // 2x oversampled grid
#define KLEN   16000
#define JTAPS  6
#define ALPHA_F 14.04f     // 2.34 * 6
#define PI_F   3.14159265358979323846f

// ---------------------------------------------------------------------------
// Static device scratch (no allocations allowed)
//   g_Rh: stage-1 out fp16, layout [p][q][c][n]
//   g_Gh: stage-2 out fp16, layout [p][k][q][c]  (coil innermost for interp)
// ---------------------------------------------------------------------------
__device__ __half2 g_Rh[PH * KOS * NCOIL * NIM];     // 65.5 MB
__device__ __half2 g_Gh[PH * KOS * KOS * NCOIL];     // 131 MB
__device__ float   g_sh[NIM];                        // apodization (sh == sw)
__device__ float   g_inv_i0a;                        // 1 / I0(alpha)

// ---------------------------------------------------------------------------
// Packed f32x2 helpers. One u2 holds the SAME component (re or im) of TWO
// columns: v_re = (colA.re, colB.re).
// ---------------------------------------------------------------------------
typedef unsigned long long u2;

__device__ __forceinline__ u2 pk2(float lo, float hi) {
    u2 r; asm("mov.b64 %0, {%1, %2};" : "=l"(r) : "f"(lo), "f"(hi)); return r;
}
__device__ __forceinline__ void upk2(float& lo, float& hi, u2 v) {
    asm("mov.b64 {%0, %1}, %2;" : "=f"(lo), "=f"(hi) : "l"(v));
}
__device__ __forceinline__ u2 dup2(float x) { return pk2(x, x); }
__device__ __forceinline__ u2 fma2(u2 a, u2 b, u2 c) {
    u2 d; asm("fma.rn.f32x2 %0, %1, %2, %3;" : "=l"(d) : "l"(a), "l"(b), "l"(c)); return d;
}
__device__ __forceinline__ u2 mul2(u2 a, u2 b) {
    u2 d; asm("mul.rn.f32x2 %0, %1, %2;" : "=l"(d) : "l"(a), "l"(b)); return d;
}
__device__ __forceinline__ u2 add2(u2 a, u2 b) {
    u2 d; asm("add.rn.f32x2 %0, %1, %2;" : "=l"(d) : "l"(a), "l"(b)); return d;
}

// (Xr,Xi) += (zr,zi) * (wr + i wi), wr/wi compile-time: branches fold.
__device__ __forceinline__ void cfma_ri(u2& Xr, u2& Xi, u2 zr, u2 zi,
                                        float wr, float wi) {
    if (wi == 0.0f) {
        if (wr == 1.0f)       { Xr = add2(Xr, zr); Xi = add2(Xi, zi); }
        else                  { Xr = fma2(zr, dup2(wr), Xr); Xi = fma2(zi, dup2(wr), Xi); }
    } else if (wr == 0.0f)    { Xr = fma2(zi, dup2(-wi), Xr); Xi = fma2(zr, dup2(wi), Xi); }
    else {
        Xr = fma2(zr, dup2(wr), Xr); Xr = fma2(zi, dup2(-wi), Xr);
        Xi = fma2(zr, dup2(wi), Xi); Xi = fma2(zi, dup2(wr), Xi);
    }
}

// ---------------------------------------------------------------------------
// Compile-time twiddle tables
// ---------------------------------------------------------------------------
__device__ constexpr float W5R[5] = {
    1.0f, 0.30901699437495f, -0.80901699437495f, -0.80901699437495f, 0.30901699437495f };
__device__ constexpr float W5I[5] = {
    0.0f, -0.95105651629515f, -0.58778525229247f, 0.58778525229247f, 0.95105651629515f };
__device__ constexpr float W20R[20] = {
    1.0f, 0.95105651629515f, 0.80901699437495f, 0.58778525229247f, 0.30901699437495f,
    0.0f, -0.30901699437495f, -0.58778525229247f, -0.80901699437495f, -0.95105651629515f,
    -1.0f, -0.95105651629515f, -0.80901699437495f, -0.58778525229247f, -0.30901699437495f,
    0.0f, 0.30901699437495f, 0.58778525229247f, 0.80901699437495f, 0.95105651629515f };
__device__ constexpr float W20I[20] = {
    0.0f, -0.30901699437495f, -0.58778525229247f, -0.80901699437495f, -0.95105651629515f,
    -1.0f, -0.95105651629515f, -0.80901699437495f, -0.58778525229247f, -0.30901699437495f,
    0.0f, 0.30901699437495f, 0.58778525229247f, 0.80901699437495f, 0.95105651629515f,
    1.0f, 0.95105651629515f, 0.80901699437495f, 0.58778525229247f, 0.30901699437495f };

// ---------------------------------------------------------------------------
// Modified Bessel I0 (Abramowitz & Stegun, rel err ~2e-7)
// ---------------------------------------------------------------------------
__device__ __forceinline__ float i0f_dev(float x) {
    if (x < 3.75f) {
        float t = x * (1.0f / 3.75f);
        t *= t;
        return 1.0f + t * (3.5156229f + t * (3.0899424f + t * (1.2067492f +
               t * (0.2659732f + t * (0.0360768f + t * 0.0045813f)))));
    } else {
        float t = 3.75f / x;
        float p = 0.39894228f + t * (0.01328592f + t * (0.00225319f +
                  t * (-0.00157565f + t * (0.00916281f + t * (-0.02057706f +
                  t * (0.02635537f + t * (-0.01647633f + t * 0.00392377f)))))));
        return p * expf(x) * rsqrtf(x);
    }
}

__global__ void init_tables_kernel() {
    int n = blockIdx.x * blockDim.x + threadIdx.x;
    if (n < NIM) {
        float i0a = i0f_dev(ALPHA_F);
        if (n == 0) g_inv_i0a = 1.0f / i0a;
        float nn = (float)(n - NIM / 2);
        float u  = nn * (1.0f / (float)KOS);
        float w  = PI_F * (float)JTAPS * u;
        float z2 = w * w - ALPHA_F * ALPHA_F;
        float z  = fmaxf(sqrtf(fabsf(z2)), 1e-6f);
        float core = (z2 > 0.0f) ? (sinf(z) / z) : (sinhf(z) / z);
        float ft = core * ((float)JTAPS / i0a);
        g_sh[n] = 1.0f / ft;
    }
}

// ---------------------------------------------------------------------------
// Four-step 640-pt DFT, zero-padded length-320 input. Block = 128 threads
// = 4 warps; each warp processes 2 columns (re/im plane packing).
//   n = 32*n1 + n2 (n1<20; nonzero n1<10),  k = k1 + 20*k2.
// Phase B: cross-lane 32-pt radix-2 DIF FFT via 64-bit shfl_xor.
// Phase C: convert to fp16, store to smem at loc = k1*32 + k2 (buffer is
//   half2 -> 23KB/block -> 5 blocks/SM = 20 warps, up from 16).
// Phase D: coalesced fp16 global copy.
// MODE 1: in = fp32 image (apodized) -> g_Rh.  MODE 2: in = g_Rh -> g_Gh.
// ---------------------------------------------------------------------------
#define SQ_PAD 9                       // buf row stride (8 cols + 1 pad)
#define BUF_H2 (KOS * SQ_PAD)          // 5760 half2 = 23040 B

template <int MODE>
__global__ __launch_bounds__(128, 5) void fft640_kernel(
    const void* __restrict__ inv, __half2* __restrict__ out)
{
    extern __shared__ __half2 buf[];   // [BUF_H2], buf[loc*SQ_PAD + c]

    const int tid  = threadIdx.x;
    const int w    = tid >> 5;         // warp 0..3
    const int lane = tid & 31;

    const int base_col = blockIdx.x * 8;
    const int colA = base_col + 2 * w;
    const int colB = colA + 1;

    // ---- load 10 inputs x 2 cols (coalesced: lane = n2), apodize MODE 1 ----
    u2 xr[10], xi[10];
    if (MODE == 1) {
        const float2* ipA = (const float2*)inv + (size_t)colA * NIM + lane;
        const float2* ipB = (const float2*)inv + (size_t)colB * NIM + lane;
        float shrA = g_sh[colA % NIM];
        float shrB = g_sh[colB % NIM];
#pragma unroll
        for (int n1 = 0; n1 < 10; n1++) {
            float2 a = ipA[n1 * 32];
            float2 b = ipB[n1 * 32];
            float sn = g_sh[n1 * 32 + lane];
            xr[n1] = pk2(a.x * (shrA * sn), b.x * (shrB * sn));
            xi[n1] = pk2(a.y * (shrA * sn), b.y * (shrB * sn));
        }
    } else {
        const __half2* ipA = (const __half2*)inv + (size_t)colA * NIM + lane;
        const __half2* ipB = (const __half2*)inv + (size_t)colB * NIM + lane;
#pragma unroll
        for (int n1 = 0; n1 < 10; n1++) {
            float2 a = __half22float2(ipA[n1 * 32]);
            float2 b = __half22float2(ipB[n1 * 32]);
            xr[n1] = pk2(a.x, b.x);
            xi[n1] = pk2(a.y, b.y);
        }
    }

    // ---- per-lane butterfly twiddles (shared by both columns) ----
    float sc_s, sc_c;
    sincospif(-(float)(lane & 15) * (1.0f / 16.0f), &sc_s, &sc_c);
    const u2 T1c = dup2((lane & 16) ? sc_c : 1.0f);
    const u2 T1s = dup2((lane & 16) ? sc_s : 0.0f);
    sincospif(-(float)(lane & 7) * (1.0f / 8.0f), &sc_s, &sc_c);
    const u2 T2c = dup2((lane & 8) ? sc_c : 1.0f);
    const u2 T2s = dup2((lane & 8) ? sc_s : 0.0f);
    sincospif(-(float)(lane & 3) * (1.0f / 4.0f), &sc_s, &sc_c);
    const u2 T3c = dup2((lane & 4) ? sc_c : 1.0f);
    const u2 T3s = dup2((lane & 4) ? sc_s : 0.0f);
    const bool t4rot = (lane & 2) && (lane & 1);
    const u2 T4c = dup2(t4rot ? 0.0f : 1.0f);
    const u2 T4s = dup2(t4rot ? -1.0f : 0.0f);
    const u2 S16 = dup2((lane & 16) ? -1.0f : 1.0f);
    const u2 S8  = dup2((lane & 8)  ? -1.0f : 1.0f);
    const u2 S4  = dup2((lane & 4)  ? -1.0f : 1.0f);
    const u2 S2  = dup2((lane & 2)  ? -1.0f : 1.0f);
    const u2 S1  = dup2((lane & 1)  ? -1.0f : 1.0f);
    const u2 NEG1 = dup2(-1.0f);
    const int br = (int)(__brev((unsigned)lane) >> 27);          // bitrev5

    // ---- twiddle chains: W640^{n2 k} = wj * (W640^{5 n2})^t, k = j+5t ----
    sincospif(-(float)lane * (1.0f / 320.0f), &sc_s, &sc_c);     // W640^{n2}
    const u2 s1r = dup2(sc_c), s1i = dup2(sc_s), s1ni = dup2(-sc_s);
    sincospif(-(float)lane * (1.0f / 64.0f), &sc_s, &sc_c);      // W640^{5 n2}
    const u2 s5r = dup2(sc_c), s5i = dup2(sc_s), s5ni = dup2(-sc_s);
    u2 wjr = dup2(1.0f), wji = dup2(0.0f), wjni = dup2(0.0f);    // W640^{n2 j}

#define BFLY_RI(H, TC, TS, SD)                                          \
    do {                                                                \
        u2 o_re = __shfl_xor_sync(0xffffffffu, v_re, (H));              \
        u2 o_im = __shfl_xor_sync(0xffffffffu, v_im, (H));              \
        u2 t_re = fma2((SD), v_re, o_re);                               \
        u2 t_im = fma2((SD), v_im, o_im);                               \
        u2 t_imn = mul2(t_im, NEG1);                                    \
        v_re = fma2(t_imn, (TS), mul2(t_re, (TC)));                     \
        v_im = fma2(t_im,  (TC), mul2(t_re, (TS)));                     \
    } while (0)

    // ---- main loop: j = k % 5 ----
#pragma unroll
    for (int j = 0; j < 5; j++) {
        const int j2 = (2 * j) % 5;
        // A1: F0..F3 for this j (recomputed; only 8 u2 live)
        u2 f0r = xr[0], f0i = xi[0];
        u2 f1r = xr[1], f1i = xi[1];
        u2 f2r = xr[2], f2i = xi[2];
        u2 f3r = xr[3], f3i = xi[3];
        cfma_ri(f0r, f0i, xr[4], xi[4], W5R[j],  W5I[j]);
        cfma_ri(f0r, f0i, xr[8], xi[8], W5R[j2], W5I[j2]);
        cfma_ri(f1r, f1i, xr[5], xi[5], W5R[j],  W5I[j]);
        cfma_ri(f1r, f1i, xr[9], xi[9], W5R[j2], W5I[j2]);
        cfma_ri(f2r, f2i, xr[6], xi[6], W5R[j],  W5I[j]);
        cfma_ri(f3r, f3i, xr[7], xi[7], W5R[j],  W5I[j]);

        // inner twiddle chain starts at wj
        u2 tr = wjr, ti = wji, tni = wjni;

#pragma unroll
        for (int t = 0; t < 4; t++) {
            const int k  = j + 5 * t;
            const int ka = (2 * k) % 20, kb = (3 * k) % 20;
            u2 Xr = f0r, Xi = f0i;
            cfma_ri(Xr, Xi, f1r, f1i, W20R[k],  W20I[k]);
            cfma_ri(Xr, Xi, f2r, f2i, W20R[ka], W20I[ka]);
            cfma_ri(Xr, Xi, f3r, f3i, W20R[kb], W20I[kb]);

            // apply W640^{n2 k}
            u2 v_re = fma2(Xi, tni, mul2(Xr, tr));
            u2 v_im = fma2(Xi, tr,  mul2(Xr, ti));
            // advance inner chain by step5
            {
                u2 nr = fma2(ti, s5ni, mul2(tr, s5r));
                u2 ni = fma2(ti, s5r,  mul2(tr, s5i));
                tr = nr; ti = ni; tni = mul2(ni, NEG1);
            }

            // 32-pt cross-lane FFT
            BFLY_RI(16, T1c, T1s, S16);
            BFLY_RI(8,  T2c, T2s, S8);
            BFLY_RI(4,  T3c, T3s, S4);
            BFLY_RI(2,  T4c, T4s, S2);
            {
                u2 o_re = __shfl_xor_sync(0xffffffffu, v_re, 1);
                u2 o_im = __shfl_xor_sync(0xffffffffu, v_im, 1);
                v_re = fma2(S1, v_re, o_re);
                v_im = fma2(S1, v_im, o_im);
            }

            // phase C: lane holds X[k2 = br] for both cols; convert to fp16
            float rA, rB, iA, iB;
            upk2(rA, rB, v_re);
            upk2(iA, iB, v_im);
            const int loc = (k * 32 + br) * SQ_PAD;
            buf[loc + 2 * w]     = __float22half2_rn(make_float2(rA, iA));
            buf[loc + 2 * w + 1] = __float22half2_rn(make_float2(rB, iB));
        }

        // advance outer chain by step1
        {
            u2 nr = fma2(wji, s1ni, mul2(wjr, s1r));
            u2 ni = fma2(wji, s1r,  mul2(wjr, s1i));
            wjr = nr; wji = ni; wjni = mul2(ni, NEG1);
        }
    }
#undef BFLY_RI
    __syncthreads();

    // ---- phase D: remapped coalesced fp16 global copy ----
    // thread -> (k2b = tid>>3 in 0..15, c = tid&7); q = k1 + 20*k2.
    const int k2b = tid >> 3;
    const int c   = tid & 7;
    size_t out_base; int stride_q;
    if (MODE == 1) {
        // col = (p*16+cc)*320 + n  ->  out[((p*640+q)*16+cc)*320 + n]
        int pc = base_col / NIM, n0 = base_col % NIM;
        int p = pc >> 4, cc = pc & 15;
        out_base = (size_t)p * (640u * 16u * 320u) + (size_t)cc * 320u
                 + (size_t)n0 + c;
        stride_q = 16 * 320;
    } else {
        // col = (p*640+qq)*16 + coil  ->  out[((p*640+kk)*640+qq)*16 + coil]
        int pq = base_col >> 4, c0 = base_col & 15;
        int p = pq / KOS, qq = pq - p * KOS;
        out_base = (size_t)p * (640u * 640u * 16u) + (size_t)qq * 16u
                 + (size_t)c0 + c;
        stride_q = 640 * 16;
    }
#pragma unroll
    for (int k1 = 0; k1 < 20; k1++) {
#pragma unroll
        for (int h = 0; h < 2; h++) {
            const int k2 = k2b + 16 * h;
            out[out_base + (size_t)(k1 + 20 * k2) * stride_q] =
                buf[(k1 * 32 + k2) * SQ_PAD + c];
        }
    }
}

// ---------------------------------------------------------------------------
// KB interpolation: 6x6 taps; each thread handles TWO adjacent coils via one
// 8B load per tap (coil-innermost fp16 G). Block = 256 = 32 points x 8 pairs.
// ---------------------------------------------------------------------------
__global__ __launch_bounds__(256) void interp_kernel(
    const float* __restrict__ traj, float2* __restrict__ out)
{
    __shared__ float s_wh[32][JTAPS], s_ww[32][JTAPS];
    __shared__ int   s_ih[32][JTAPS], s_iw[32][JTAPS];
    __shared__ float s_pr[32], s_pi[32];

    const int tid = threadIdx.x;
    const int cp  = tid & 7;                      // coil pair 0..7
    const int li  = tid >> 3;                     // point within block 0..31
    const int p   = blockIdx.y;
    const int l   = blockIdx.x * 32 + li;

    const float inv_i0a = g_inv_i0a;

    if (cp < 2) {
        float om = traj[(long)(p * 2 + cp) * KLEN + l];
        float t  = om * (320.0f / PI_F);
        float base = floorf(t - 3.0f);
#pragma unroll
        for (int j = 0; j < JTAPS; j++) {
            float kf  = base + (float)(j + 1);
            float u   = t - kf;
            float ua  = u * (1.0f / 3.0f);
            float arg = fmaxf(1.0f - ua * ua, 0.0f);
            float w   = i0f_dev(ALPHA_F * sqrtf(arg)) * inv_i0a;
            int ki  = (int)kf;
            int idx = ki % KOS; if (idx < 0) idx += KOS;
            if (cp == 0) { s_wh[li][j] = w; s_ih[li][j] = idx; }
            else         { s_ww[li][j] = w; s_iw[li][j] = idx; }
        }
        if (cp == 0) {
            float om1 = traj[(long)(p * 2 + 1) * KLEN + l];
            float th  = 160.0f * (om + om1);
            float sp, cpn;
            sincosf(th, &sp, &cpn);
            s_pr[li] = cpn; s_pi[li] = sp;
        }
    }
    __syncthreads();

    float wh[JTAPS], ww[JTAPS];
    int   ihx[JTAPS], iwx[JTAPS];
#pragma unroll
    for (int j = 0; j < JTAPS; j++) {
        wh[j]  = s_wh[li][j];
        ww[j]  = s_ww[li][j];
        ihx[j] = s_ih[li][j];
        iwx[j] = s_iw[li][j] * 8;     // in uint2 (8B = 2 coils) units
    }
    const float pr = s_pr[li], pi = s_pi[li];

    // Base pointer at coil pair: coils 2cp, 2cp+1 are one aligned uint2
    const uint2* Gp = (const uint2*)(g_Gh + (size_t)p * (640u * 640u * 16u))
                      + cp;
    float ar0 = 0.0f, ai0 = 0.0f, ar1 = 0.0f, ai1 = 0.0f;
#pragma unroll
    for (int j1 = 0; j1 < JTAPS; j1++) {
        const uint2* row = Gp + (size_t)ihx[j1] * (640u * 8u);
        const float w1 = wh[j1];
#pragma unroll
        for (int j2 = 0; j2 < JTAPS; j2++) {
            uint2 pair = row[iwx[j2]];
            float2 v0 = __half22float2(*(const __half2*)&pair.x);
            float2 v1 = __half22float2(*(const __half2*)&pair.y);
            float  w = w1 * ww[j2];
            ar0 = fmaf(v0.x, w, ar0);
            ai0 = fmaf(v0.y, w, ai0);
            ar1 = fmaf(v1.x, w, ar1);
            ai1 = fmaf(v1.y, w, ai1);
        }
    }
    const float sc = 1.0f / 640.0f;               // ortho norm
    float2 o0, o1;
    o0.x = (ar0 * pr - ai0 * pi) * sc;
    o0.y = (ar0 * pi + ai0 * pr) * sc;
    o1.x = (ar1 * pr - ai1 * pi) * sc;
    o1.y = (ar1 * pi + ai1 * pr) * sc;
    out[(long)((p * NCOIL + 2 * cp) * KLEN) + l] = o0;
    out[(long)((p * NCOIL + 2 * cp + 1) * KLEN) + l] = o1;
}

// ---------------------------------------------------------------------------
// Launch
// ---------------------------------------------------------------------------
extern "C" void kernel_launch(void* const* d_in, const int* in_sizes, int n_in,
                              void* d_out, int out_size)
{
    const float2* image = (const float2*)d_in[0];   // (1,5,8,2,320,320,2)
    const float*  traj  = (const float*)d_in[1];    // (5,2,16000)

    __half2 *Rhp, *Ghp;
    cudaGetSymbolAddress((void**)&Rhp, g_Rh);
    cudaGetSymbolAddress((void**)&Ghp, g_Gh);

    const int smem_bytes = BUF_H2 * (int)sizeof(__half2);   // 23040
    cudaFuncSetAttribute(fft640_kernel<1>,
                         cudaFuncAttributeMaxDynamicSharedMemorySize, smem_bytes);
    cudaFuncSetAttribute(fft640_kernel<2>,
                         cudaFuncAttributeMaxDynamicSharedMemorySize, smem_bytes);

    init_tables_kernel<<<2, 256>>>();

    // Stage 1: FFT along m (width), apodized.  cols = (p,c,n): 25600
    fft640_kernel<1><<<(PH * NCOIL * NIM) / 8, 128, smem_bytes>>>(
        (const void*)image, Rhp);

    // Stage 2: FFT along n (height).  cols = (p,q,c): 51200
    fft640_kernel<2><<<(PH * KOS * NCOIL) / 8, 128, smem_bytes>>>(
        (const void*)Rhp, Ghp);

    // Stage 3: KB interpolation + recentering phase + ortho scale
    {
        dim3 grid(KLEN / 32, PH);
        interp_kernel<<<grid, 256>>>(traj, (float2*)d_out);
    }
}

// round 13
// speedup vs baseline: 1.0017x; 1.0017x over previous
#include <cuda_runtime.h>
#include <cuda_bf16.h>
#include <cuda_fp16.h>
#include <math.h>

// Problem constants
#define PH     5
#define NCOIL  16          // ch*d = 8*2
#define NIM    320         // H = W
#define KOS    640         // 2x oversampled grid
#define KLEN   16000
#define JTAPS  6
#define ALPHA_F 14.04f     // 2.34 * 6
#define PI_F   3.14159265358979323846f

// ---------------------------------------------------------------------------
// Static device scratch (no allocations allowed)
//   g_Rh: stage-1 out fp16, layout [p][q][c][n]
//   g_Gh: stage-2 out fp16, layout [p][k][q][c]  (coil innermost for interp)
// ---------------------------------------------------------------------------
__device__ __half2 g_Rh[PH * KOS * NCOIL * NIM];     // 65.5 MB
__device__ __half2 g_Gh[PH * KOS * KOS * NCOIL];     // 131 MB
__device__ float   g_sh[NIM];                        // apodization (sh == sw)
__device__ float   g_inv_i0a;                        // 1 / I0(alpha)

// ---------------------------------------------------------------------------
// Packed f32x2 helpers. One u2 holds the SAME component (re or im) of TWO
// columns: v_re = (colA.re, colB.re).
// ---------------------------------------------------------------------------
typedef unsigned long long u2;

__device__ __forceinline__ u2 pk2(float lo, float hi) {
    u2 r; asm("mov.b64 %0, {%1, %2};" : "=l"(r) : "f"(lo), "f"(hi)); return r;
}
__device__ __forceinline__ void upk2(float& lo, float& hi, u2 v) {
    asm("mov.b64 {%0, %1}, %2;" : "=f"(lo), "=f"(hi) : "l"(v));
}
__device__ __forceinline__ u2 dup2(float x) { return pk2(x, x); }
__device__ __forceinline__ u2 fma2(u2 a, u2 b, u2 c) {
    u2 d; asm("fma.rn.f32x2 %0, %1, %2, %3;" : "=l"(d) : "l"(a), "l"(b), "l"(c)); return d;
}
__device__ __forceinline__ u2 mul2(u2 a, u2 b) {
    u2 d; asm("mul.rn.f32x2 %0, %1, %2;" : "=l"(d) : "l"(a), "l"(b)); return d;
}
__device__ __forceinline__ u2 add2(u2 a, u2 b) {
    u2 d; asm("add.rn.f32x2 %0, %1, %2;" : "=l"(d) : "l"(a), "l"(b)); return d;
}

// (Xr,Xi) += (zr,zi) * (wr + i wi), wr/wi compile-time: branches fold.
__device__ __forceinline__ void cfma_ri(u2& Xr, u2& Xi, u2 zr, u2 zi,
                                        float wr, float wi) {
    if (wi == 0.0f) {
        if (wr == 1.0f)       { Xr = add2(Xr, zr); Xi = add2(Xi, zi); }
        else                  { Xr = fma2(zr, dup2(wr), Xr); Xi = fma2(zi, dup2(wr), Xi); }
    } else if (wr == 0.0f)    { Xr = fma2(zi, dup2(-wi), Xr); Xi = fma2(zr, dup2(wi), Xi); }
    else {
        Xr = fma2(zr, dup2(wr), Xr); Xr = fma2(zi, dup2(-wi), Xr);
        Xi = fma2(zr, dup2(wi), Xi); Xi = fma2(zi, dup2(wr), Xi);
    }
}

// ---------------------------------------------------------------------------
// Compile-time twiddle tables
// ---------------------------------------------------------------------------
__device__ constexpr float W5R[5] = {
    1.0f, 0.30901699437495f, -0.80901699437495f, -0.80901699437495f, 0.30901699437495f };
__device__ constexpr float W5I[5] = {
    0.0f, -0.95105651629515f, -0.58778525229247f, 0.58778525229247f, 0.95105651629515f };
__device__ constexpr float W20R[20] = {
    1.0f, 0.95105651629515f, 0.80901699437495f, 0.58778525229247f, 0.30901699437495f,
    0.0f, -0.30901699437495f, -0.58778525229247f, -0.80901699437495f, -0.95105651629515f,
    -1.0f, -0.95105651629515f, -0.80901699437495f, -0.58778525229247f, -0.30901699437495f,
    0.0f, 0.30901699437495f, 0.58778525229247f, 0.80901699437495f, 0.95105651629515f };
__device__ constexpr float W20I[20] = {
    0.0f, -0.30901699437495f, -0.58778525229247f, -0.80901699437495f, -0.95105651629515f,
    -1.0f, -0.95105651629515f, -0.80901699437495f, -0.58778525229247f, -0.30901699437495f,
    0.0f, 0.30901699437495f, 0.58778525229247f, 0.80901699437495f, 0.95105651629515f,
    1.0f, 0.95105651629515f, 0.80901699437495f, 0.58778525229247f, 0.30901699437495f };

// ---------------------------------------------------------------------------
// Modified Bessel I0 (Abramowitz & Stegun, rel err ~2e-7)
// ---------------------------------------------------------------------------
__device__ __forceinline__ float i0f_dev(float x) {
    if (x < 3.75f) {
        float t = x * (1.0f / 3.75f);
        t *= t;
        return 1.0f + t * (3.5156229f + t * (3.0899424f + t * (1.2067492f +
               t * (0.2659732f + t * (0.0360768f + t * 0.0045813f)))));
    } else {
        float t = 3.75f / x;
        float p = 0.39894228f + t * (0.01328592f + t * (0.00225319f +
                  t * (-0.00157565f + t * (0.00916281f + t * (-0.02057706f +
                  t * (0.02635537f + t * (-0.01647633f + t * 0.00392377f)))))));
        return p * expf(x) * rsqrtf(x);
    }
}

__global__ void init_tables_kernel() {
    int n = blockIdx.x * blockDim.x + threadIdx.x;
    if (n < NIM) {
        float i0a = i0f_dev(ALPHA_F);
        if (n == 0) g_inv_i0a = 1.0f / i0a;
        float nn = (float)(n - NIM / 2);
        float u  = nn * (1.0f / (float)KOS);
        float w  = PI_F * (float)JTAPS * u;
        float z2 = w * w - ALPHA_F * ALPHA_F;
        float z  = fmaxf(sqrtf(fabsf(z2)), 1e-6f);
        float core = (z2 > 0.0f) ? (sinf(z) / z) : (sinhf(z) / z);
        float ft = core * ((float)JTAPS / i0a);
        g_sh[n] = 1.0f / ft;
    }
}

// ---------------------------------------------------------------------------
// Four-step 640-pt DFT, zero-padded length-320 input. Block = 256 threads
// = 8 warps; block processes 32 CONSECUTIVE columns (each warp runs the
// 2-column re/im-packed pipeline twice). Phase D then writes, per output
// index q, 32 consecutive half2 = one full 128B line, warp-coalesced.
//   n = 32*n1 + n2 (n1<20; nonzero n1<10),  k = k1 + 20*k2.
// MODE 1: in = fp32 image (apodized) -> g_Rh.  MODE 2: in = g_Rh -> g_Gh.
// ---------------------------------------------------------------------------
#define SQ_PAD 33                      // buf row stride (32 cols + 1 pad)
#define BUF_H2 (KOS * SQ_PAD)          // 21120 half2 = 84480 B

template <int MODE>
__global__ __launch_bounds__(256, 2) void fft640_kernel(
    const void* __restrict__ inv, __half2* __restrict__ out)
{
    extern __shared__ __half2 buf[];   // [BUF_H2], buf[loc*SQ_PAD + col_local]

    const int tid  = threadIdx.x;
    const int w    = tid >> 5;         // warp 0..7
    const int lane = tid & 31;

    const int base_col = blockIdx.x * 32;

    // ---- per-lane butterfly twiddles (shared by both columns, both passes) ----
    float sc_s, sc_c;
    sincospif(-(float)(lane & 15) * (1.0f / 16.0f), &sc_s, &sc_c);
    const u2 T1c = dup2((lane & 16) ? sc_c : 1.0f);
    const u2 T1s = dup2((lane & 16) ? sc_s : 0.0f);
    sincospif(-(float)(lane & 7) * (1.0f / 8.0f), &sc_s, &sc_c);
    const u2 T2c = dup2((lane & 8) ? sc_c : 1.0f);
    const u2 T2s = dup2((lane & 8) ? sc_s : 0.0f);
    sincospif(-(float)(lane & 3) * (1.0f / 4.0f), &sc_s, &sc_c);
    const u2 T3c = dup2((lane & 4) ? sc_c : 1.0f);
    const u2 T3s = dup2((lane & 4) ? sc_s : 0.0f);
    const bool t4rot = (lane & 2) && (lane & 1);
    const u2 T4c = dup2(t4rot ? 0.0f : 1.0f);
    const u2 T4s = dup2(t4rot ? -1.0f : 0.0f);
    const u2 S16 = dup2((lane & 16) ? -1.0f : 1.0f);
    const u2 S8  = dup2((lane & 8)  ? -1.0f : 1.0f);
    const u2 S4  = dup2((lane & 4)  ? -1.0f : 1.0f);
    const u2 S2  = dup2((lane & 2)  ? -1.0f : 1.0f);
    const u2 S1  = dup2((lane & 1)  ? -1.0f : 1.0f);
    const u2 NEG1 = dup2(-1.0f);
    const int br = (int)(__brev((unsigned)lane) >> 27);          // bitrev5

    // twiddle chain steps: W640^{n2}, W640^{5 n2}
    sincospif(-(float)lane * (1.0f / 320.0f), &sc_s, &sc_c);
    const u2 s1r = dup2(sc_c), s1i = dup2(sc_s), s1ni = dup2(-sc_s);
    sincospif(-(float)lane * (1.0f / 64.0f), &sc_s, &sc_c);
    const u2 s5r = dup2(sc_c), s5i = dup2(sc_s), s5ni = dup2(-sc_s);

#define BFLY_RI(H, TC, TS, SD)                                          \
    do {                                                                \
        u2 o_re = __shfl_xor_sync(0xffffffffu, v_re, (H));              \
        u2 o_im = __shfl_xor_sync(0xffffffffu, v_im, (H));              \
        u2 t_re = fma2((SD), v_re, o_re);                               \
        u2 t_im = fma2((SD), v_im, o_im);                               \
        u2 t_imn = mul2(t_im, NEG1);                                    \
        v_re = fma2(t_imn, (TS), mul2(t_re, (TC)));                     \
        v_im = fma2(t_im,  (TC), mul2(t_re, (TS)));                     \
    } while (0)

    // ==================== two passes: 2 columns each ====================
#pragma unroll 1
    for (int pass = 0; pass < 2; pass++) {
        const int cl  = 4 * w + 2 * pass;         // col_local of colA
        const int colA = base_col + cl;
        const int colB = colA + 1;

        // ---- load 10 inputs x 2 cols (coalesced), apodize MODE 1 ----
        u2 xr[10], xi[10];
        if (MODE == 1) {
            const float2* ipA = (const float2*)inv + (size_t)colA * NIM + lane;
            const float2* ipB = (const float2*)inv + (size_t)colB * NIM + lane;
            float shrA = g_sh[colA % NIM];
            float shrB = g_sh[colB % NIM];
#pragma unroll
            for (int n1 = 0; n1 < 10; n1++) {
                float2 a = ipA[n1 * 32];
                float2 b = ipB[n1 * 32];
                float sn = g_sh[n1 * 32 + lane];
                xr[n1] = pk2(a.x * (shrA * sn), b.x * (shrB * sn));
                xi[n1] = pk2(a.y * (shrA * sn), b.y * (shrB * sn));
            }
        } else {
            const __half2* ipA = (const __half2*)inv + (size_t)colA * NIM + lane;
            const __half2* ipB = (const __half2*)inv + (size_t)colB * NIM + lane;
#pragma unroll
            for (int n1 = 0; n1 < 10; n1++) {
                float2 a = __half22float2(ipA[n1 * 32]);
                float2 b = __half22float2(ipB[n1 * 32]);
                xr[n1] = pk2(a.x, b.x);
                xi[n1] = pk2(a.y, b.y);
            }
        }

        u2 wjr = dup2(1.0f), wji = dup2(0.0f), wjni = dup2(0.0f);

        // ---- main loop: j = k % 5 ----
#pragma unroll
        for (int j = 0; j < 5; j++) {
            const int j2 = (2 * j) % 5;
            u2 f0r = xr[0], f0i = xi[0];
            u2 f1r = xr[1], f1i = xi[1];
            u2 f2r = xr[2], f2i = xi[2];
            u2 f3r = xr[3], f3i = xi[3];
            cfma_ri(f0r, f0i, xr[4], xi[4], W5R[j],  W5I[j]);
            cfma_ri(f0r, f0i, xr[8], xi[8], W5R[j2], W5I[j2]);
            cfma_ri(f1r, f1i, xr[5], xi[5], W5R[j],  W5I[j]);
            cfma_ri(f1r, f1i, xr[9], xi[9], W5R[j2], W5I[j2]);
            cfma_ri(f2r, f2i, xr[6], xi[6], W5R[j],  W5I[j]);
            cfma_ri(f3r, f3i, xr[7], xi[7], W5R[j],  W5I[j]);

            u2 tr = wjr, ti = wji, tni = wjni;

#pragma unroll
            for (int t = 0; t < 4; t++) {
                const int k  = j + 5 * t;
                const int ka = (2 * k) % 20, kb = (3 * k) % 20;
                u2 Xr = f0r, Xi = f0i;
                cfma_ri(Xr, Xi, f1r, f1i, W20R[k],  W20I[k]);
                cfma_ri(Xr, Xi, f2r, f2i, W20R[ka], W20I[ka]);
                cfma_ri(Xr, Xi, f3r, f3i, W20R[kb], W20I[kb]);

                u2 v_re = fma2(Xi, tni, mul2(Xr, tr));
                u2 v_im = fma2(Xi, tr,  mul2(Xr, ti));
                {
                    u2 nr = fma2(ti, s5ni, mul2(tr, s5r));
                    u2 ni = fma2(ti, s5r,  mul2(tr, s5i));
                    tr = nr; ti = ni; tni = mul2(ni, NEG1);
                }

                BFLY_RI(16, T1c, T1s, S16);
                BFLY_RI(8,  T2c, T2s, S8);
                BFLY_RI(4,  T3c, T3s, S4);
                BFLY_RI(2,  T4c, T4s, S2);
                {
                    u2 o_re = __shfl_xor_sync(0xffffffffu, v_re, 1);
                    u2 o_im = __shfl_xor_sync(0xffffffffu, v_im, 1);
                    v_re = fma2(S1, v_re, o_re);
                    v_im = fma2(S1, v_im, o_im);
                }

                // phase C: lane holds X[k2 = br] for both cols; fp16 store
                float rA, rB, iA, iB;
                upk2(rA, rB, v_re);
                upk2(iA, iB, v_im);
                const int loc = (k * 32 + br) * SQ_PAD + cl;
                buf[loc]     = __float22half2_rn(make_float2(rA, iA));
                buf[loc + 1] = __float22half2_rn(make_float2(rB, iB));
            }

            {
                u2 nr = fma2(wji, s1ni, mul2(wjr, s1r));
                u2 ni = fma2(wji, s1r,  mul2(wjr, s1i));
                wjr = nr; wji = ni; wjni = mul2(ni, NEG1);
            }
        }
    }
#undef BFLY_RI
    __syncthreads();

    // ---- phase D: warp = one (k1,k2); lane = col_local -> 128B coalesced ----
    const int cl = tid & 31;           // col_local
    const int w0 = tid >> 5;           // 0..7
    size_t out_base; int stride_q;
    if (MODE == 1) {
        // col = (p*16+cc)*320 + n ; out[((p*640+q)*16+cc)*320 + n]
        int pc = base_col / NIM, n0 = base_col % NIM;
        int p = pc >> 4, cc = pc & 15;
        out_base = (size_t)p * (640u * 16u * 320u) + (size_t)cc * 320u + (size_t)n0;
        stride_q = 16 * 320;
    } else {
        // col = (p*640+qq)*16 + coil ; out[((p*640+kk)*640+qq)*16 + coil]
        int pq = base_col >> 4;        // base coil = 0 (base_col mult of 32)
        int p = pq / KOS, qq = pq - p * KOS;
        out_base = (size_t)p * (640u * 640u * 16u) + (size_t)qq * 16u;
        stride_q = 640 * 16;
    }
#pragma unroll
    for (int k1 = 0; k1 < 20; k1++) {
#pragma unroll
        for (int h = 0; h < 4; h++) {
            const int k2 = w0 + 8 * h;
            out[out_base + (size_t)(k1 + 20 * k2) * stride_q + cl] =
                buf[(k1 * 32 + k2) * SQ_PAD + cl];
        }
    }
}

// ---------------------------------------------------------------------------
// KB interpolation: 6x6 taps; each thread handles TWO adjacent coils via one
// 8B load per tap (coil-innermost fp16 G). Block = 256 = 32 points x 8 pairs.
// ---------------------------------------------------------------------------
__global__ __launch_bounds__(256) void interp_kernel(
    const float* __restrict__ traj, float2* __restrict__ out)
{
    __shared__ float s_wh[32][JTAPS], s_ww[32][JTAPS];
    __shared__ int   s_ih[32][JTAPS], s_iw[32][JTAPS];
    __shared__ float s_pr[32], s_pi[32];

    const int tid = threadIdx.x;
    const int cp  = tid & 7;                      // coil pair 0..7
    const int li  = tid >> 3;                     // point within block 0..31
    const int p   = blockIdx.y;
    const int l   = blockIdx.x * 32 + li;

    const float inv_i0a = g_inv_i0a;

    if (cp < 2) {
        float om = traj[(long)(p * 2 + cp) * KLEN + l];
        float t  = om * (320.0f / PI_F);
        float base = floorf(t - 3.0f);
#pragma unroll
        for (int j = 0; j < JTAPS; j++) {
            float kf  = base + (float)(j + 1);
            float u   = t - kf;
            float ua  = u * (1.0f / 3.0f);
            float arg = fmaxf(1.0f - ua * ua, 0.0f);
            float w   = i0f_dev(ALPHA_F * sqrtf(arg)) * inv_i0a;
            int ki  = (int)kf;
            int idx = ki % KOS; if (idx < 0) idx += KOS;
            if (cp == 0) { s_wh[li][j] = w; s_ih[li][j] = idx; }
            else         { s_ww[li][j] = w; s_iw[li][j] = idx; }
        }
        if (cp == 0) {
            float om1 = traj[(long)(p * 2 + 1) * KLEN + l];
            float th  = 160.0f * (om + om1);
            float sp, cpn;
            sincosf(th, &sp, &cpn);
            s_pr[li] = cpn; s_pi[li] = sp;
        }
    }
    __syncthreads();

    float wh[JTAPS], ww[JTAPS];
    int   ihx[JTAPS], iwx[JTAPS];
#pragma unroll
    for (int j = 0; j < JTAPS; j++) {
        wh[j]  = s_wh[li][j];
        ww[j]  = s_ww[li][j];
        ihx[j] = s_ih[li][j];
        iwx[j] = s_iw[li][j] * 8;     // in uint2 (8B = 2 coils) units
    }
    const float pr = s_pr[li], pi = s_pi[li];

    const uint2* Gp = (const uint2*)(g_Gh + (size_t)p * (640u * 640u * 16u))
                      + cp;
    float ar0 = 0.0f, ai0 = 0.0f, ar1 = 0.0f, ai1 = 0.0f;
#pragma unroll
    for (int j1 = 0; j1 < JTAPS; j1++) {
        const uint2* row = Gp + (size_t)ihx[j1] * (640u * 8u);
        const float w1 = wh[j1];
#pragma unroll
        for (int j2 = 0; j2 < JTAPS; j2++) {
            uint2 pair = row[iwx[j2]];
            float2 v0 = __half22float2(*(const __half2*)&pair.x);
            float2 v1 = __half22float2(*(const __half2*)&pair.y);
            float  w = w1 * ww[j2];
            ar0 = fmaf(v0.x, w, ar0);
            ai0 = fmaf(v0.y, w, ai0);
            ar1 = fmaf(v1.x, w, ar1);
            ai1 = fmaf(v1.y, w, ai1);
        }
    }
    const float sc = 1.0f / 640.0f;               // ortho norm
    float2 o0, o1;
    o0.x = (ar0 * pr - ai0 * pi) * sc;
    o0.y = (ar0 * pi + ai0 * pr) * sc;
    o1.x = (ar1 * pr - ai1 * pi) * sc;
    o1.y = (ar1 * pi + ai1 * pr) * sc;
    out[(long)((p * NCOIL + 2 * cp) * KLEN) + l] = o0;
    out[(long)((p * NCOIL + 2 * cp + 1) * KLEN) + l] = o1;
}

// ---------------------------------------------------------------------------
// Launch
// ---------------------------------------------------------------------------
extern "C" void kernel_launch(void* const* d_in, const int* in_sizes, int n_in,
                              void* d_out, int out_size)
{
    const float2* image = (const float2*)d_in[0];   // (1,5,8,2,320,320,2)
    const float*  traj  = (const float*)d_in[1];    // (5,2,16000)

    __half2 *Rhp, *Ghp;
    cudaGetSymbolAddress((void**)&Rhp, g_Rh);
    cudaGetSymbolAddress((void**)&Ghp, g_Gh);

    const int smem_bytes = BUF_H2 * (int)sizeof(__half2);   // 84480
    cudaFuncSetAttribute(fft640_kernel<1>,
                         cudaFuncAttributeMaxDynamicSharedMemorySize, smem_bytes);
    cudaFuncSetAttribute(fft640_kernel<2>,
                         cudaFuncAttributeMaxDynamicSharedMemorySize, smem_bytes);

    init_tables_kernel<<<2, 256>>>();

    // Stage 1: FFT along m (width), apodized.  cols = (p,c,n): 25600 -> 800 blocks
    fft640_kernel<1><<<(PH * NCOIL * NIM) / 32, 256, smem_bytes>>>(
        (const void*)image, Rhp);

    // Stage 2: FFT along n (height).  cols = (p,q,c): 51200 -> 1600 blocks
    fft640_kernel<2><<<(PH * KOS * NCOIL) / 32, 256, smem_bytes>>>(
        (const void*)Rhp, Ghp);

    // Stage 3: KB interpolation + recentering phase + ortho scale
    {
        dim3 grid(KLEN / 32, PH);
        interp_kernel<<<grid, 256>>>(traj, (float2*)d_out);
    }
}